// round 6
// baseline (speedup 1.0000x reference)
#include <cuda_runtime.h>

#define NN 50000
#define EE 800000
#define DD 64
#define GG 64

typedef unsigned long long ull;

// ---------------- scratch (device globals; accessed ONLY by symbol in device code)
__device__ int   d_is64;
__device__ int   d_batch[NN];
__device__ int   d_deg[NN];
__device__ int   d_rowptr[NN + 1];
__device__ int   d_cursor[NN];
__device__ int2  d_csr[EE];            // (col, edge_attr bits)
__device__ int   d_degmaxbits[GG];     // per-graph max degree, float bits
__device__ float d_e0[NN * DD];        // x_emb ping
__device__ float d_e1[NN * DD];        // x_emb pong
__device__ float d_nein[NN * DD];      // [0:62] relu node_edge embed, [63] degree_norm
__device__ float d_xaggemb[NN * DD];   // x_agg_emb
__device__ float d_gsum[GG * DD];
__device__ int   d_gcnt[GG];
__device__ float d_rg[GG * DD];

// ---------------- f32x2 helpers ---------------------------------------------
__device__ __forceinline__ ull pack2(float x, float y) {
    ull r; asm("mov.b64 %0, {%1, %2};" : "=l"(r) : "f"(x), "f"(y)); return r;
}
__device__ __forceinline__ float2 unpack2(ull v) {
    float2 f; asm("mov.b64 {%0, %1}, %2;" : "=f"(f.x), "=f"(f.y) : "l"(v)); return f;
}
__device__ __forceinline__ void ffma2(ull& d, ull a, ull b) {
    asm("fma.rn.f32x2 %0, %1, %2, %3;" : "=l"(d) : "l"(a), "l"(b), "l"(d));
}

// ---------------- setup -----------------------------------------------------

__global__ void k_zero() {
    int i = blockIdx.x * blockDim.x + threadIdx.x;
    int st = gridDim.x * blockDim.x;
    if (i == 0) d_is64 = 1;
    for (int j = i; j < NN; j += st) d_deg[j] = 0;
    for (int j = i; j < GG; j += st) { d_degmaxbits[j] = 0; d_gcnt[j] = 0; }
    for (int j = i; j < GG * DD; j += st) d_gsum[j] = 0.f;
}

// int64 vs int32 sniff (validated in R5): int32 data read as int64 lands out of
// [0,NN) somewhere among 800k elements.
__global__ void k_detect(const long long* __restrict__ ei) {
    int e = blockIdx.x * blockDim.x + threadIdx.x;
    if (e < EE) {
        long long v = ei[e];
        if (v < 0 || v >= NN) d_is64 = 0;
    }
}

// fused: in-degree histogram + batch convert + per-graph degree max
__global__ void k_cvt_count(const void* __restrict__ ei, const void* __restrict__ bt,
                            const float* __restrict__ degree) {
    int i = blockIdx.x * blockDim.x + threadIdx.x;
    int s = d_is64;
    if (i < EE) {
        int r = s ? (int)((const long long*)ei)[EE + i] : ((const int*)ei)[EE + i];
        atomicAdd(&d_deg[r], 1);
    }
    if (i < NN) {
        int b = s ? (int)((const long long*)bt)[i] : ((const int*)bt)[i];
        d_batch[i] = b;
        atomicMax(&d_degmaxbits[b], __float_as_int(degree[i]));
    }
}

// single-block exclusive scan deg -> rowptr (+cursor)
__global__ void k_scan() {
    __shared__ int ssum[1024];
    int t = threadIdx.x;
    const int per = (NN + 1023) / 1024;
    int base = t * per;
    int s = 0;
    for (int i = 0; i < per; i++) { int idx = base + i; if (idx < NN) s += d_deg[idx]; }
    ssum[t] = s;
    __syncthreads();
    for (int off = 1; off < 1024; off <<= 1) {
        int v = 0;
        if (t >= off) v = ssum[t - off];
        __syncthreads();
        if (t >= off) ssum[t] += v;
        __syncthreads();
    }
    int run = (t == 0) ? 0 : ssum[t - 1];
    for (int i = 0; i < per; i++) {
        int idx = base + i;
        if (idx < NN) { d_rowptr[idx] = run; d_cursor[idx] = run; run += d_deg[idx]; }
    }
    if (t == 0) d_rowptr[NN] = EE;
}

// CSR fill straight from raw edge_index (no col/row intermediates)
__global__ void k_fill(const void* __restrict__ ei, const float* __restrict__ ea) {
    int e = blockIdx.x * blockDim.x + threadIdx.x;
    if (e >= EE) return;
    int s = d_is64;
    int c = s ? (int)((const long long*)ei)[e]      : ((const int*)ei)[e];
    int r = s ? (int)((const long long*)ei)[EE + e] : ((const int*)ei)[EE + e];
    int p = atomicAdd(&d_cursor[r], 1);
    d_csr[p] = make_int2(c, __float_as_int(ea[e]));
}

// ---------------- embeddings -------------------------------------------------

// x_emb = relu(x @ W_en + b_en) -> d_e0
__global__ void k_xemb(const float* __restrict__ x, const float* __restrict__ W,
                       const float* __restrict__ b) {
    int i = blockIdx.x * blockDim.x + threadIdx.x;
    if (i >= NN * DD) return;
    int n = i >> 6, c = i & 63;
    const float* xr = x + n * 7;
    float s = b[c];
#pragma unroll
    for (int k = 0; k < 7; k++) s += xr[k] * W[k * DD + c];
    d_e0[i] = fmaxf(s, 0.f);
}

// node+edge embed: warp per node; mean of [x[col](7), edge_attr(1)] -> GEMV 8x63 relu
__global__ void k_ne(const float* __restrict__ x, const float* __restrict__ W,
                     const float* __restrict__ b) {
    int warp = (blockIdx.x * blockDim.x + threadIdx.x) >> 5;
    int lane = threadIdx.x & 31;
    if (warp >= NN) return;
    int n = warp;
    int beg = d_rowptr[n], end = d_rowptr[n + 1];
    float acc[8] = {0, 0, 0, 0, 0, 0, 0, 0};
    for (int j = beg + lane; j < end; j += 32) {
        int2 cv = d_csr[j];
        const float* xr = x + cv.x * 7;
#pragma unroll
        for (int k = 0; k < 7; k++) acc[k] += xr[k];
        acc[7] += __int_as_float(cv.y);
    }
#pragma unroll
    for (int k = 0; k < 8; k++)
#pragma unroll
        for (int off = 16; off; off >>= 1) acc[k] += __shfl_xor_sync(0xffffffffu, acc[k], off);
    float inv = 1.f / (float)max(end - beg, 1);
#pragma unroll
    for (int k = 0; k < 8; k++) acc[k] *= inv;
    float o0 = b[lane];
    float o1 = (lane < 31) ? b[lane + 32] : 0.f;
#pragma unroll
    for (int k = 0; k < 8; k++) {
        o0 += acc[k] * W[k * 63 + lane];
        if (lane < 31) o1 += acc[k] * W[k * 63 + lane + 32];
    }
    d_nein[n * DD + lane] = fmaxf(o0, 0.f);
    if (lane < 31) d_nein[n * DD + 32 + lane] = fmaxf(o1, 0.f);
    if (lane == 31) d_nein[n * DD + 63] = __int_as_float(d_degmaxbits[d_batch[n]]);
}

// x_agg_emb = relu([node_edge, degree_norm] @ W_agg + b_agg)
__global__ void k_aggemb(const float* __restrict__ W, const float* __restrict__ b) {
    int i = blockIdx.x * blockDim.x + threadIdx.x;
    if (i >= NN * DD) return;
    int n = i >> 6, c = i & 63;
    const float* in = d_nein + n * DD;
    float s = b[c];
#pragma unroll
    for (int k = 0; k < DD; k++) s += in[k] * W[k * DD + c];
    d_xaggemb[i] = fmaxf(s, 0.f);
}

// ---------------- fused message-passing layer (persistent, f32x2) -----------
// 256 thr = 8 warps; each warp owns 4 nodes per quad; lane owns output cols
// (2*lane, 2*lane+1). Staging stores duplicated (v,v) pairs at [k][node] so a
// single LDS.128 broadcast feeds two nodes' FFMA2.
// dyn smem: Wm 32KB + Wu 32KB + staging 8 warps * 4KB = 96KB -> 2 blocks/SM.

#define LAYER_SMEM (32768 + 32768 + 8 * 512 * 8)

__global__ void __launch_bounds__(256) k_layer(
    int flip,   // 0: e0 -> e1 ; 1: e1 -> e0
    const float2* __restrict__ Wm2, const float* __restrict__ bm,
    const float2* __restrict__ Wu2, const float* __restrict__ bu) {
    const float* xin  = flip ? d_e1 : d_e0;
    float*       xout = flip ? d_e0 : d_e1;
    extern __shared__ float2 sm2[];
    float2* sWm = sm2;                 // [128][32] pairs: pair j of row k = cols (2j,2j+1)
    float2* sWu = sm2 + 4096;
    float2* sSt = sm2 + 8192;          // per warp: 512 float2 = [k in 0..127][i in 0..3]
    int t = threadIdx.x;
    for (int i = t; i < 4096; i += 256) { sWm[i] = Wm2[i]; sWu[i] = Wu2[i]; }
    __syncthreads();

    int warp = t >> 5, lane = t & 31;
    float2* sv = sSt + warp * 512;
    const ull*  swm = (const ull*)sWm;
    const ull*  swu = (const ull*)sWu;
    const ulonglong2* svq = (const ulonglong2*)sv;

    ull bmp = ((const ull*)bm)[lane];  // bias pair (2lane, 2lane+1)
    ull bup = ((const ull*)bu)[lane];

    const int quads = (NN + 3) / 4;
    for (int q = blockIdx.x * 8 + warp; q < quads; q += gridDim.x * 8) {
        int nbase = q * 4;

        // Phase A: x_agg gather (mean of ea * xin[col]) + stage [x_agg, x_agg_emb]
#pragma unroll
        for (int i = 0; i < 4; i++) {
            int n = nbase + i;
            ull a = 0;                         // packed (0.f, 0.f)
            float2 g = make_float2(0.f, 0.f);
            if (n < NN) {
                int beg = d_rowptr[n], end = d_rowptr[n + 1];
                for (int j = beg; j < end; j++) {
                    int2 cv = d_csr[j];
                    float w = __int_as_float(cv.y);
                    ull xv = ((const ull*)(xin + cv.x * DD))[lane];  // cols 2lane,2lane+1
                    ffma2(a, pack2(w, w), xv);
                }
                float inv = 1.f / (float)max(end - beg, 1);
                float2 af = unpack2(a);
                a = pack2(af.x * inv, af.y * inv);
                g = ((const float2*)(d_xaggemb + n * DD))[lane];
            }
            float2 af = unpack2(a);
            sv[(2 * lane) * 4 + i]       = make_float2(af.x, af.x);
            sv[(2 * lane + 1) * 4 + i]   = make_float2(af.y, af.y);
            sv[(64 + 2 * lane) * 4 + i]     = make_float2(g.x, g.x);
            sv[(64 + 2 * lane + 1) * 4 + i] = make_float2(g.y, g.y);
        }
        __syncwarp();

        // Phase B: m = relu([x_agg, x_agg_emb] @ Wm + bm)
        ull a0 = bmp, a1 = bmp, a2 = bmp, a3 = bmp;
#pragma unroll 4
        for (int k = 0; k < 128; k++) {
            ull w = swm[k * 32 + lane];
            ulonglong2 p0 = svq[k * 2];       // nodes 0,1 duplicated pairs
            ulonglong2 p1 = svq[k * 2 + 1];   // nodes 2,3
            ffma2(a0, w, p0.x); ffma2(a1, w, p0.y);
            ffma2(a2, w, p1.x); ffma2(a3, w, p1.y);
        }
        __syncwarp();

        // Phase C: stage [x_emb_old, relu(m)]
        {
            float2 m[4];
            m[0] = unpack2(a0); m[1] = unpack2(a1); m[2] = unpack2(a2); m[3] = unpack2(a3);
#pragma unroll
            for (int i = 0; i < 4; i++) {
                int n = nbase + i;
                float2 xe = make_float2(0.f, 0.f);
                if (n < NN) xe = ((const float2*)(xin + n * DD))[lane];
                sv[(2 * lane) * 4 + i]     = make_float2(xe.x, xe.x);
                sv[(2 * lane + 1) * 4 + i] = make_float2(xe.y, xe.y);
                float mx = fmaxf(m[i].x, 0.f), my = fmaxf(m[i].y, 0.f);
                sv[(64 + 2 * lane) * 4 + i]     = make_float2(mx, mx);
                sv[(64 + 2 * lane + 1) * 4 + i] = make_float2(my, my);
            }
        }
        __syncwarp();

        // Phase D: x_emb_new = relu([x_emb, m] @ Wu + bu)
        ull u0 = bup, u1 = bup, u2 = bup, u3 = bup;
#pragma unroll 4
        for (int k = 0; k < 128; k++) {
            ull w = swu[k * 32 + lane];
            ulonglong2 p0 = svq[k * 2];
            ulonglong2 p1 = svq[k * 2 + 1];
            ffma2(u0, w, p0.x); ffma2(u1, w, p0.y);
            ffma2(u2, w, p1.x); ffma2(u3, w, p1.y);
        }
        {
            ull us[4] = {u0, u1, u2, u3};
#pragma unroll
            for (int i = 0; i < 4; i++) {
                int n = nbase + i;
                if (n < NN) {
                    float2 uf = unpack2(us[i]);
                    ((float2*)(xout + n * DD))[lane] =
                        make_float2(fmaxf(uf.x, 0.f), fmaxf(uf.y, 0.f));
                }
            }
        }
        __syncwarp();
    }
}

// ---------------- readout ----------------------------------------------------

__global__ void k_gsum() {
    __shared__ float sg[GG * DD];
    __shared__ int sc[GG];
    int t = threadIdx.x;
    for (int i = t; i < GG * DD; i += blockDim.x) sg[i] = 0.f;
    for (int i = t; i < GG; i += blockDim.x) sc[i] = 0;
    __syncthreads();
    int per = (NN + gridDim.x - 1) / gridDim.x;
    int nb = blockIdx.x * per;
    int ne = min(NN, nb + per);
    int col = t & 63, sub = t >> 6;
    for (int n = nb + sub; n < ne; n += 4) {
        int g = d_batch[n];
        atomicAdd(&sg[g * DD + col], d_e1[n * DD + col]);
        if (col == 0) atomicAdd(&sc[g], 1);
    }
    __syncthreads();
    for (int i = t; i < GG * DD; i += blockDim.x) atomicAdd(&d_gsum[i], sg[i]);
    for (int i = t; i < GG; i += blockDim.x) atomicAdd(&d_gcnt[i], sc[i]);
}

__global__ void k_gproj(const float* __restrict__ Wg, const float* __restrict__ bg) {
    int g = blockIdx.x, c = threadIdx.x;
    float inv = 1.f / (float)max(d_gcnt[g], 1);
    float s = bg[c];
    const float* row = d_gsum + g * DD;
#pragma unroll
    for (int k = 0; k < DD; k++) s += row[k] * inv * Wg[k * DD + c];
    d_rg[g * DD + c] = fmaxf(s, 0.f);
}

__global__ void k_final(const float* __restrict__ Wr, const float* __restrict__ br,
                        float* __restrict__ out) {
    int warp = (blockIdx.x * blockDim.x + threadIdx.x) >> 5;
    int lane = threadIdx.x & 31;
    if (warp >= NN) return;
    int n = warp;
    int g = d_batch[n];
    const float* rg = d_rg + g * DD;
    const float* xr = d_e1 + n * DD;
    float p = rg[lane] * Wr[lane] + rg[lane + 32] * Wr[lane + 32]
            + xr[lane] * Wr[64 + lane] + xr[lane + 32] * Wr[96 + lane];
#pragma unroll
    for (int off = 16; off; off >>= 1) p += __shfl_xor_sync(0xffffffffu, p, off);
    if (lane == 0) out[n] = p + br[0];
}

// ---------------- launch ------------------------------------------------------

extern "C" void kernel_launch(void* const* d_in, const int* in_sizes, int n_in,
                              void* d_out, int out_size) {
    int base = (n_in > 5 && in_sizes[5] == 1) ? 6 : 5;

    const float* x      = (const float*)d_in[0];
    const void*  ei     = d_in[1];
    const float* ea     = (const float*)d_in[2];
    const void*  batch  = d_in[3];
    const float* degree = (const float*)d_in[4];
    const float* W_en  = (const float*)d_in[base + 0];
    const float* b_en  = (const float*)d_in[base + 1];
    const float* W_ene = (const float*)d_in[base + 2];
    const float* b_ene = (const float*)d_in[base + 3];
    const float* W_agg = (const float*)d_in[base + 4];
    const float* b_agg = (const float*)d_in[base + 5];
    const float* Wm    = (const float*)d_in[base + 6];
    const float* bm    = (const float*)d_in[base + 7];
    const float* Wu    = (const float*)d_in[base + 8];
    const float* bu    = (const float*)d_in[base + 9];
    const float* W_g   = (const float*)d_in[base + 10];
    const float* b_g   = (const float*)d_in[base + 11];
    const float* W_r   = (const float*)d_in[base + 12];
    const float* b_r   = (const float*)d_in[base + 13];
    float* out = (float*)d_out;

    cudaFuncSetAttribute(k_layer, cudaFuncAttributeMaxDynamicSharedMemorySize, LAYER_SMEM);

    const int TB = 256;
    int gE  = (EE + TB - 1) / TB;
    int gND = (NN * DD + TB - 1) / TB;
    int gNW = (NN * 32 + TB - 1) / TB;

    k_zero<<<64, TB>>>();
    k_detect<<<gE, TB>>>((const long long*)ei);
    k_cvt_count<<<gE, TB>>>(ei, batch, degree);
    k_scan<<<1, 1024>>>();
    k_fill<<<gE, TB>>>(ei, ea);

    k_xemb<<<gND, TB>>>(x, W_en, b_en);
    k_ne<<<gNW, TB>>>(x, W_ene, b_ene);
    k_aggemb<<<gND, TB>>>(W_agg, b_agg);

    const int GL = 296;   // persistent: 2 blocks/SM
    k_layer<<<GL, TB, LAYER_SMEM>>>(0, (const float2*)(Wm + 0 * 8192), bm + 0 * 64,
                                       (const float2*)(Wu + 0 * 8192), bu + 0 * 64);
    k_layer<<<GL, TB, LAYER_SMEM>>>(1, (const float2*)(Wm + 1 * 8192), bm + 1 * 64,
                                       (const float2*)(Wu + 1 * 8192), bu + 1 * 64);
    k_layer<<<GL, TB, LAYER_SMEM>>>(0, (const float2*)(Wm + 2 * 8192), bm + 2 * 64,
                                       (const float2*)(Wu + 2 * 8192), bu + 2 * 64);

    k_gsum<<<148, TB>>>();
    k_gproj<<<GG, DD>>>(W_g, b_g);
    k_final<<<gNW, TB>>>(W_r, b_r, out);

    (void)in_sizes; (void)n_in; (void)out_size; (void)degree;
}

// round 9
// speedup vs baseline: 1.7430x; 1.7430x over previous
#include <cuda_runtime.h>

#define NN 50000
#define EE 800000
#define DD 64
#define GG 64

#define SCAN_B 256
#define NSB ((NN + SCAN_B - 1) / SCAN_B)   // 196 blocks

// ---------------- scratch (device globals; accessed ONLY by symbol in device code)
__device__ int   d_is64;
__device__ int   d_col[EE];
__device__ int   d_row[EE];
__device__ int   d_batch[NN];
__device__ int   d_deg[NN];
__device__ int   d_rowptr[NN + 1];
__device__ int   d_cursor[NN];
__device__ int   d_csrcol[EE];
__device__ float d_csrval[EE];
__device__ int   d_bsum[NSB];
__device__ int   d_boff[NSB];
__device__ int   d_degmaxbits[GG];     // per-graph max degree, float bits (degree >= 0)
__device__ float d_e0[NN * DD];        // x_emb ping
__device__ float d_e1[NN * DD];        // x_emb pong
__device__ float d_nein[NN * DD];      // [0:62] relu node_edge embed, [63] degree_norm
__device__ float d_xaggemb[NN * DD];   // x_agg_emb
__device__ float d_gsum[GG * DD];
__device__ int   d_gcnt[GG];
__device__ float d_rg[GG * DD];        // relu(g_agg @ W_g + b_g)

// ---------------- setup -----------------------------------------------------

__global__ void k_zero() {
    int i = blockIdx.x * blockDim.x + threadIdx.x;
    int st = gridDim.x * blockDim.x;
    if (i == 0) d_is64 = 1;
    for (int j = i; j < NN; j += st) d_deg[j] = 0;
    for (int j = i; j < GG; j += st) { d_degmaxbits[j] = 0; d_gcnt[j] = 0; }
    for (int j = i; j < GG * DD; j += st) d_gsum[j] = 0.f;
}

// int64 vs int32 sniff (validated): int32 data read as int64 lands out of
// [0,NN) somewhere among 800k elements.
__global__ void k_detect(const long long* __restrict__ ei) {
    int e = blockIdx.x * blockDim.x + threadIdx.x;
    if (e < EE) {
        long long v = ei[e];
        if (v < 0 || v >= NN) d_is64 = 0;
    }
}

__global__ void k_cvt(const void* __restrict__ ei, const void* __restrict__ bt) {
    int i = blockIdx.x * blockDim.x + threadIdx.x;
    int s = d_is64;
    if (i < EE) {
        if (s) {
            d_col[i] = (int)((const long long*)ei)[i];
            d_row[i] = (int)((const long long*)ei)[EE + i];
        } else {
            d_col[i] = ((const int*)ei)[i];
            d_row[i] = ((const int*)ei)[EE + i];
        }
    }
    if (i < NN)
        d_batch[i] = s ? (int)((const long long*)bt)[i] : ((const int*)bt)[i];
}

__global__ void k_count(const float* __restrict__ degree) {
    int i = blockIdx.x * blockDim.x + threadIdx.x;
    if (i < EE) atomicAdd(&d_deg[d_row[i]], 1);
    if (i < NN) atomicMax(&d_degmaxbits[d_batch[i]], __float_as_int(degree[i]));
}

// ---- parallel exclusive scan of d_deg (replaces 126us single-block scan) ----

__global__ void k_bsum() {
    __shared__ int s[SCAN_B];
    int t = threadIdx.x;
    int i = blockIdx.x * SCAN_B + t;
    s[t] = (i < NN) ? d_deg[i] : 0;
    __syncthreads();
    for (int off = SCAN_B / 2; off; off >>= 1) {
        if (t < off) s[t] += s[t + off];
        __syncthreads();
    }
    if (t == 0) d_bsum[blockIdx.x] = s[0];
}

__global__ void k_bscan() {   // single block, NSB(=196) <= 256 elements
    __shared__ int s[SCAN_B];
    int t = threadIdx.x;
    s[t] = (t < NSB) ? d_bsum[t] : 0;
    __syncthreads();
    for (int off = 1; off < SCAN_B; off <<= 1) {
        int v = (t >= off) ? s[t - off] : 0;
        __syncthreads();
        s[t] += v;
        __syncthreads();
    }
    if (t < NSB) d_boff[t] = (t == 0) ? 0 : s[t - 1];
}

__global__ void k_pscan() {
    __shared__ int s[SCAN_B];
    int t = threadIdx.x;
    int i = blockIdx.x * SCAN_B + t;
    int v = (i < NN) ? d_deg[i] : 0;
    s[t] = v;
    __syncthreads();
    for (int off = 1; off < SCAN_B; off <<= 1) {
        int u = (t >= off) ? s[t - off] : 0;
        __syncthreads();
        s[t] += u;
        __syncthreads();
    }
    int excl = s[t] - v + d_boff[blockIdx.x];
    if (i < NN) { d_rowptr[i] = excl; d_cursor[i] = excl; }
    if (i == 0) d_rowptr[NN] = EE;
}

__global__ void k_fill(const float* __restrict__ ea) {
    int e = blockIdx.x * blockDim.x + threadIdx.x;
    if (e >= EE) return;
    int r = d_row[e];
    int p = atomicAdd(&d_cursor[r], 1);
    d_csrcol[p] = d_col[e];
    d_csrval[p] = ea[e];
}

// ---------------- embeddings -------------------------------------------------

// x_emb = relu(x @ W_en + b_en) -> d_e0
__global__ void k_xemb(const float* __restrict__ x, const float* __restrict__ W,
                       const float* __restrict__ b) {
    int i = blockIdx.x * blockDim.x + threadIdx.x;
    if (i >= NN * DD) return;
    int n = i >> 6, c = i & 63;
    const float* xr = x + n * 7;
    float s = b[c];
#pragma unroll
    for (int k = 0; k < 7; k++) s += xr[k] * W[k * DD + c];
    d_e0[i] = fmaxf(s, 0.f);
}

// node+edge embed: warp per node; mean of [x[col](7), edge_attr(1)] -> GEMV 8x63 relu
__global__ void k_ne(const float* __restrict__ x, const float* __restrict__ W,
                     const float* __restrict__ b) {
    int warp = (blockIdx.x * blockDim.x + threadIdx.x) >> 5;
    int lane = threadIdx.x & 31;
    if (warp >= NN) return;
    int n = warp;
    int beg = d_rowptr[n], end = d_rowptr[n + 1];
    float acc[8] = {0, 0, 0, 0, 0, 0, 0, 0};
    for (int j = beg + lane; j < end; j += 32) {
        int c = d_csrcol[j];
        const float* xr = x + c * 7;
#pragma unroll
        for (int k = 0; k < 7; k++) acc[k] += xr[k];
        acc[7] += d_csrval[j];
    }
#pragma unroll
    for (int k = 0; k < 8; k++)
#pragma unroll
        for (int off = 16; off; off >>= 1) acc[k] += __shfl_xor_sync(0xffffffffu, acc[k], off);
    float inv = 1.f / (float)max(end - beg, 1);
#pragma unroll
    for (int k = 0; k < 8; k++) acc[k] *= inv;
    float o0 = b[lane];
    float o1 = (lane < 31) ? b[lane + 32] : 0.f;
#pragma unroll
    for (int k = 0; k < 8; k++) {
        o0 += acc[k] * W[k * 63 + lane];
        if (lane < 31) o1 += acc[k] * W[k * 63 + lane + 32];
    }
    d_nein[n * DD + lane] = fmaxf(o0, 0.f);
    if (lane < 31) d_nein[n * DD + 32 + lane] = fmaxf(o1, 0.f);
    if (lane == 31) d_nein[n * DD + 63] = __int_as_float(d_degmaxbits[d_batch[n]]);
}

// x_agg_emb = relu([node_edge, degree_norm] @ W_agg + b_agg)
__global__ void k_aggemb(const float* __restrict__ W, const float* __restrict__ b) {
    int i = blockIdx.x * blockDim.x + threadIdx.x;
    if (i >= NN * DD) return;
    int n = i >> 6, c = i & 63;
    const float* in = d_nein + n * DD;
    float s = b[c];
#pragma unroll
    for (int k = 0; k < DD; k++) s += in[k] * W[k * DD + c];
    d_xaggemb[i] = fmaxf(s, 0.f);
}

// ---------------- fused message-passing layer (R5 proven config) ------------
// 256 thr = 8 warps; warp owns 4 nodes (amortizes smem weight reads 4x)
// dyn smem: Wm 32KB + Wu 32KB + staging 16KB = 80KB

#define NPW 4
#define LAYER_SMEM ((8192 + 8192 + 8 * NPW * 128) * (int)sizeof(float))

__global__ void __launch_bounds__(256) k_layer(
    int flip,   // 0: e0 -> e1 ; 1: e1 -> e0
    const float* __restrict__ Wm, const float* __restrict__ bm,
    const float* __restrict__ Wu, const float* __restrict__ bu) {
    const float* xin  = flip ? d_e1 : d_e0;
    float*       xout = flip ? d_e0 : d_e1;
    extern __shared__ float sm[];
    float* sWm = sm;
    float* sWu = sm + 8192;
    float* sIn = sm + 16384;
    int t = threadIdx.x;
    for (int i = t; i < 8192; i += 256) { sWm[i] = Wm[i]; sWu[i] = Wu[i]; }
    __syncthreads();

    int warp = t >> 5, lane = t & 31;
    float* sv = sIn + warp * (NPW * 128);
    int nbase = blockIdx.x * (8 * NPW) + warp * NPW;

    // Phase A: x_agg = mean_{e->n} ea[e]*xin[col[e]]; stage [x_agg, x_agg_emb]
#pragma unroll
    for (int i = 0; i < NPW; i++) {
        int n = nbase + i;
        if (n < NN) {
            int beg = d_rowptr[n], end = d_rowptr[n + 1];
            float a0 = 0.f, a1 = 0.f;
            for (int j = beg; j < end; j++) {
                int c = d_csrcol[j];
                float w = d_csrval[j];
                const float* xr = xin + c * DD;
                a0 += w * xr[lane];
                a1 += w * xr[lane + 32];
            }
            float inv = 1.f / (float)max(end - beg, 1);
            sv[i * 128 + lane]      = a0 * inv;
            sv[i * 128 + 32 + lane] = a1 * inv;
            sv[i * 128 + 64 + lane] = d_xaggemb[n * DD + lane];
            sv[i * 128 + 96 + lane] = d_xaggemb[n * DD + 32 + lane];
        } else {
            sv[i * 128 + lane] = 0.f; sv[i * 128 + 32 + lane] = 0.f;
            sv[i * 128 + 64 + lane] = 0.f; sv[i * 128 + 96 + lane] = 0.f;
        }
    }
    __syncwarp();

    // Phase B: m = relu([x_agg, x_agg_emb] @ Wm + bm)
    float m0[NPW], m1[NPW];
    {
        float b0 = bm[lane], b1 = bm[lane + 32];
#pragma unroll
        for (int i = 0; i < NPW; i++) { m0[i] = b0; m1[i] = b1; }
    }
#pragma unroll 4
    for (int k = 0; k < 128; k++) {
        float w0 = sWm[k * DD + lane];
        float w1 = sWm[k * DD + lane + 32];
#pragma unroll
        for (int i = 0; i < NPW; i++) {
            float v = sv[i * 128 + k];
            m0[i] += v * w0;
            m1[i] += v * w1;
        }
    }
    __syncwarp();

    // Phase C: stage [x_emb_old, relu(m)]
#pragma unroll
    for (int i = 0; i < NPW; i++) {
        int n = nbase + i;
        if (n < NN) {
            sv[i * 128 + lane]      = xin[n * DD + lane];
            sv[i * 128 + 32 + lane] = xin[n * DD + 32 + lane];
        } else {
            sv[i * 128 + lane] = 0.f; sv[i * 128 + 32 + lane] = 0.f;
        }
        sv[i * 128 + 64 + lane] = fmaxf(m0[i], 0.f);
        sv[i * 128 + 96 + lane] = fmaxf(m1[i], 0.f);
    }
    __syncwarp();

    // Phase D: x_emb_new = relu([x_emb, m] @ Wu + bu)
    float u0[NPW], u1[NPW];
    {
        float b0 = bu[lane], b1 = bu[lane + 32];
#pragma unroll
        for (int i = 0; i < NPW; i++) { u0[i] = b0; u1[i] = b1; }
    }
#pragma unroll 4
    for (int k = 0; k < 128; k++) {
        float w0 = sWu[k * DD + lane];
        float w1 = sWu[k * DD + lane + 32];
#pragma unroll
        for (int i = 0; i < NPW; i++) {
            float v = sv[i * 128 + k];
            u0[i] += v * w0;
            u1[i] += v * w1;
        }
    }
#pragma unroll
    for (int i = 0; i < NPW; i++) {
        int n = nbase + i;
        if (n < NN) {
            xout[n * DD + lane]      = fmaxf(u0[i], 0.f);
            xout[n * DD + 32 + lane] = fmaxf(u1[i], 0.f);
        }
    }
}

// ---------------- readout ----------------------------------------------------

__global__ void k_gsum() {
    __shared__ float sg[GG * DD];
    __shared__ int sc[GG];
    int t = threadIdx.x;
    for (int i = t; i < GG * DD; i += blockDim.x) sg[i] = 0.f;
    for (int i = t; i < GG; i += blockDim.x) sc[i] = 0;
    __syncthreads();
    int per = (NN + gridDim.x - 1) / gridDim.x;
    int nb = blockIdx.x * per;
    int ne = min(NN, nb + per);
    int col = t & 63, sub = t >> 6;
    for (int n = nb + sub; n < ne; n += 4) {
        int g = d_batch[n];
        atomicAdd(&sg[g * DD + col], d_e1[n * DD + col]);
        if (col == 0) atomicAdd(&sc[g], 1);
    }
    __syncthreads();
    for (int i = t; i < GG * DD; i += blockDim.x) atomicAdd(&d_gsum[i], sg[i]);
    for (int i = t; i < GG; i += blockDim.x) atomicAdd(&d_gcnt[i], sc[i]);
}

__global__ void k_gproj(const float* __restrict__ Wg, const float* __restrict__ bg) {
    int g = blockIdx.x, c = threadIdx.x;
    float inv = 1.f / (float)max(d_gcnt[g], 1);
    float s = bg[c];
    const float* row = d_gsum + g * DD;
#pragma unroll
    for (int k = 0; k < DD; k++) s += row[k] * inv * Wg[k * DD + c];
    d_rg[g * DD + c] = fmaxf(s, 0.f);
}

__global__ void k_final(const float* __restrict__ Wr, const float* __restrict__ br,
                        float* __restrict__ out) {
    int warp = (blockIdx.x * blockDim.x + threadIdx.x) >> 5;
    int lane = threadIdx.x & 31;
    if (warp >= NN) return;
    int n = warp;
    int g = d_batch[n];
    const float* rg = d_rg + g * DD;
    const float* xr = d_e1 + n * DD;
    float p = rg[lane] * Wr[lane] + rg[lane + 32] * Wr[lane + 32]
            + xr[lane] * Wr[64 + lane] + xr[lane + 32] * Wr[96 + lane];
#pragma unroll
    for (int off = 16; off; off >>= 1) p += __shfl_xor_sync(0xffffffffu, p, off);
    if (lane == 0) out[n] = p + br[0];
}

// ---------------- launch ------------------------------------------------------

extern "C" void kernel_launch(void* const* d_in, const int* in_sizes, int n_in,
                              void* d_out, int out_size) {
    int base = (n_in > 5 && in_sizes[5] == 1) ? 6 : 5;

    const float* x      = (const float*)d_in[0];
    const void*  ei     = d_in[1];
    const float* ea     = (const float*)d_in[2];
    const void*  batch  = d_in[3];
    const float* degree = (const float*)d_in[4];
    const float* W_en  = (const float*)d_in[base + 0];
    const float* b_en  = (const float*)d_in[base + 1];
    const float* W_ene = (const float*)d_in[base + 2];
    const float* b_ene = (const float*)d_in[base + 3];
    const float* W_agg = (const float*)d_in[base + 4];
    const float* b_agg = (const float*)d_in[base + 5];
    const float* Wm    = (const float*)d_in[base + 6];
    const float* bm    = (const float*)d_in[base + 7];
    const float* Wu    = (const float*)d_in[base + 8];
    const float* bu    = (const float*)d_in[base + 9];
    const float* W_g   = (const float*)d_in[base + 10];
    const float* b_g   = (const float*)d_in[base + 11];
    const float* W_r   = (const float*)d_in[base + 12];
    const float* b_r   = (const float*)d_in[base + 13];
    float* out = (float*)d_out;

    cudaFuncSetAttribute(k_layer, cudaFuncAttributeMaxDynamicSharedMemorySize, LAYER_SMEM);

    const int TB = 256;
    int gE  = (EE + TB - 1) / TB;
    int gND = (NN * DD + TB - 1) / TB;
    int gNW = (NN * 32 + TB - 1) / TB;

    k_zero<<<64, TB>>>();
    k_detect<<<gE, TB>>>((const long long*)ei);
    k_cvt<<<gE, TB>>>(ei, batch);
    k_count<<<gE, TB>>>(degree);
    k_bsum<<<NSB, SCAN_B>>>();
    k_bscan<<<1, SCAN_B>>>();
    k_pscan<<<NSB, SCAN_B>>>();
    k_fill<<<gE, TB>>>(ea);

    k_xemb<<<gND, TB>>>(x, W_en, b_en);
    k_ne<<<gNW, TB>>>(x, W_ene, b_ene);
    k_aggemb<<<gND, TB>>>(W_agg, b_agg);

    int nodes_per_blk = 8 * NPW;
    int gL = (NN + nodes_per_blk - 1) / nodes_per_blk;
    k_layer<<<gL, TB, LAYER_SMEM>>>(0, Wm + 0 * 8192, bm + 0 * 64, Wu + 0 * 8192, bu + 0 * 64);
    k_layer<<<gL, TB, LAYER_SMEM>>>(1, Wm + 1 * 8192, bm + 1 * 64, Wu + 1 * 8192, bu + 1 * 64);
    k_layer<<<gL, TB, LAYER_SMEM>>>(0, Wm + 2 * 8192, bm + 2 * 64, Wu + 2 * 8192, bu + 2 * 64);

    k_gsum<<<148, TB>>>();
    k_gproj<<<GG, DD>>>(W_g, b_g);
    k_final<<<gNW, TB>>>(W_r, b_r, out);

    (void)in_sizes; (void)n_in; (void)out_size; (void)degree;
}

// round 11
// speedup vs baseline: 1.7974x; 1.0312x over previous
#include <cuda_runtime.h>

#define NN 50000
#define EE 800000
#define DD 64
#define GG 64

#define SCAN_B 256
#define NSB ((NN + SCAN_B - 1) / SCAN_B)   // 196 blocks

// ---------------- scratch (device globals; accessed ONLY by symbol in device code)
__device__ int   d_is64;
__device__ int   d_batch[NN];
__device__ int   d_deg[NN];
__device__ int   d_rowptr[NN + 1];
__device__ int   d_cursor[NN];
__device__ int2  d_csr[EE];            // (col, edge_attr float bits)
__device__ int   d_bsum[NSB];
__device__ int   d_boff[NSB];
__device__ int   d_degmaxbits[GG];     // per-graph max degree, float bits (degree >= 0)
__device__ float d_e0[NN * DD];        // x_emb ping
__device__ float d_e1[NN * DD];        // x_emb pong
__device__ float d_nein[NN * DD];      // [0:62] relu node_edge embed, [63] degree_norm
__device__ float d_xaggemb[NN * DD];   // x_agg_emb
__device__ float d_gsum[GG * DD];
__device__ int   d_gcnt[GG];
__device__ float d_rg[GG * DD];        // relu(g_agg @ W_g + b_g)

// ---------------- setup -----------------------------------------------------

__global__ void k_zero() {
    int i = blockIdx.x * blockDim.x + threadIdx.x;
    int st = gridDim.x * blockDim.x;
    if (i == 0) d_is64 = 1;
    for (int j = i; j < NN; j += st) d_deg[j] = 0;
    for (int j = i; j < GG; j += st) { d_degmaxbits[j] = 0; d_gcnt[j] = 0; }
    for (int j = i; j < GG * DD; j += st) d_gsum[j] = 0.f;
}

// int64 vs int32 sniff (validated): int32 data read as int64 lands out of
// [0,NN) somewhere among 800k elements.
__global__ void k_detect(const long long* __restrict__ ei) {
    int e = blockIdx.x * blockDim.x + threadIdx.x;
    if (e < EE) {
        long long v = ei[e];
        if (v < 0 || v >= NN) d_is64 = 0;
    }
}

// fused: in-degree histogram + batch convert + per-graph degree max (R6-proven)
__global__ void k_cvt_count(const void* __restrict__ ei, const void* __restrict__ bt,
                            const float* __restrict__ degree) {
    int i = blockIdx.x * blockDim.x + threadIdx.x;
    int s = d_is64;
    if (i < EE) {
        int r = s ? (int)((const long long*)ei)[EE + i] : ((const int*)ei)[EE + i];
        atomicAdd(&d_deg[r], 1);
    }
    if (i < NN) {
        int b = s ? (int)((const long long*)bt)[i] : ((const int*)bt)[i];
        d_batch[i] = b;
        atomicMax(&d_degmaxbits[b], __float_as_int(degree[i]));
    }
}

// ---- parallel exclusive scan of d_deg ----

__global__ void k_bsum() {
    __shared__ int s[SCAN_B];
    int t = threadIdx.x;
    int i = blockIdx.x * SCAN_B + t;
    s[t] = (i < NN) ? d_deg[i] : 0;
    __syncthreads();
    for (int off = SCAN_B / 2; off; off >>= 1) {
        if (t < off) s[t] += s[t + off];
        __syncthreads();
    }
    if (t == 0) d_bsum[blockIdx.x] = s[0];
}

__global__ void k_bscan() {   // single block, NSB(=196) <= 256 elements
    __shared__ int s[SCAN_B];
    int t = threadIdx.x;
    s[t] = (t < NSB) ? d_bsum[t] : 0;
    __syncthreads();
    for (int off = 1; off < SCAN_B; off <<= 1) {
        int v = (t >= off) ? s[t - off] : 0;
        __syncthreads();
        s[t] += v;
        __syncthreads();
    }
    if (t < NSB) d_boff[t] = (t == 0) ? 0 : s[t - 1];
}

__global__ void k_pscan() {
    __shared__ int s[SCAN_B];
    int t = threadIdx.x;
    int i = blockIdx.x * SCAN_B + t;
    int v = (i < NN) ? d_deg[i] : 0;
    s[t] = v;
    __syncthreads();
    for (int off = 1; off < SCAN_B; off <<= 1) {
        int u = (t >= off) ? s[t - off] : 0;
        __syncthreads();
        s[t] += u;
        __syncthreads();
    }
    int excl = s[t] - v + d_boff[blockIdx.x];
    if (i < NN) { d_rowptr[i] = excl; d_cursor[i] = excl; }
    if (i == 0) d_rowptr[NN] = EE;
}

// CSR fill straight from raw edge_index (R6-proven; no intermediates)
__global__ void k_fill(const void* __restrict__ ei, const float* __restrict__ ea) {
    int e = blockIdx.x * blockDim.x + threadIdx.x;
    if (e >= EE) return;
    int s = d_is64;
    int c = s ? (int)((const long long*)ei)[e]      : ((const int*)ei)[e];
    int r = s ? (int)((const long long*)ei)[EE + e] : ((const int*)ei)[EE + e];
    int p = atomicAdd(&d_cursor[r], 1);
    d_csr[p] = make_int2(c, __float_as_int(ea[e]));
}

// ---------------- embeddings -------------------------------------------------

// x_emb = relu(x @ W_en + b_en) -> d_e0
__global__ void k_xemb(const float* __restrict__ x, const float* __restrict__ W,
                       const float* __restrict__ b) {
    int i = blockIdx.x * blockDim.x + threadIdx.x;
    if (i >= NN * DD) return;
    int n = i >> 6, c = i & 63;
    const float* xr = x + n * 7;
    float s = b[c];
#pragma unroll
    for (int k = 0; k < 7; k++) s += xr[k] * W[k * DD + c];
    d_e0[i] = fmaxf(s, 0.f);
}

// node+edge embed: warp per node; mean of [x[col](7), edge_attr(1)] -> GEMV 8x63 relu
__global__ void k_ne(const float* __restrict__ x, const float* __restrict__ W,
                     const float* __restrict__ b) {
    int warp = (blockIdx.x * blockDim.x + threadIdx.x) >> 5;
    int lane = threadIdx.x & 31;
    if (warp >= NN) return;
    int n = warp;
    int beg = d_rowptr[n], end = d_rowptr[n + 1];
    float acc[8] = {0, 0, 0, 0, 0, 0, 0, 0};
    for (int j = beg + lane; j < end; j += 32) {
        int2 cv = d_csr[j];
        const float* xr = x + cv.x * 7;
#pragma unroll
        for (int k = 0; k < 7; k++) acc[k] += xr[k];
        acc[7] += __int_as_float(cv.y);
    }
#pragma unroll
    for (int k = 0; k < 8; k++)
#pragma unroll
        for (int off = 16; off; off >>= 1) acc[k] += __shfl_xor_sync(0xffffffffu, acc[k], off);
    float inv = 1.f / (float)max(end - beg, 1);
#pragma unroll
    for (int k = 0; k < 8; k++) acc[k] *= inv;
    float o0 = b[lane];
    float o1 = (lane < 31) ? b[lane + 32] : 0.f;
#pragma unroll
    for (int k = 0; k < 8; k++) {
        o0 += acc[k] * W[k * 63 + lane];
        if (lane < 31) o1 += acc[k] * W[k * 63 + lane + 32];
    }
    d_nein[n * DD + lane] = fmaxf(o0, 0.f);
    if (lane < 31) d_nein[n * DD + 32 + lane] = fmaxf(o1, 0.f);
    if (lane == 31) d_nein[n * DD + 63] = __int_as_float(d_degmaxbits[d_batch[n]]);
}

// x_agg_emb = relu([node_edge, degree_norm] @ W_agg + b_agg)
__global__ void k_aggemb(const float* __restrict__ W, const float* __restrict__ b) {
    int i = blockIdx.x * blockDim.x + threadIdx.x;
    if (i >= NN * DD) return;
    int n = i >> 6, c = i & 63;
    const float* in = d_nein + n * DD;
    float s = b[c];
#pragma unroll
    for (int k = 0; k < DD; k++) s += in[k] * W[k * DD + c];
    d_xaggemb[i] = fmaxf(s, 0.f);
}

// ---------------- fused message-passing layer --------------------------------
// R5 structure (1563 blocks, 8 warps, 4 nodes/warp, scalar FFMA, broadcast
// weight LDS) with ONE change: staging is [k][node] so the MLP inner loop reads
// all 4 nodes' k-value with a single uniform LDS.128 broadcast (14 -> 11
// issues per k per 4 nodes).
// dyn smem: Wm 32KB + Wu 32KB + staging 8 warps * 2KB = 80KB

#define NPW 4
#define LAYER_SMEM ((8192 + 8192 + 8 * NPW * 128) * (int)sizeof(float))

__global__ void __launch_bounds__(256) k_layer(
    int flip,   // 0: e0 -> e1 ; 1: e1 -> e0
    const float* __restrict__ Wm, const float* __restrict__ bm,
    const float* __restrict__ Wu, const float* __restrict__ bu) {
    const float* xin  = flip ? d_e1 : d_e0;
    float*       xout = flip ? d_e0 : d_e1;
    extern __shared__ float sm[];
    float* sWm = sm;
    float* sWu = sm + 8192;
    float* sIn = sm + 16384;
    int t = threadIdx.x;
    for (int i = t; i < 8192; i += 256) { sWm[i] = Wm[i]; sWu[i] = Wu[i]; }
    __syncthreads();

    int warp = t >> 5, lane = t & 31;
    float* sv = sIn + warp * (NPW * 128);           // [k in 0..127][i in 0..3]
    const float4* sv4 = (const float4*)sv;
    int nbase = blockIdx.x * (8 * NPW) + warp * NPW;

    // Phase A: x_agg = mean_{e->n} ea[e]*xin[col[e]]; stage [x_agg, x_agg_emb]
#pragma unroll
    for (int i = 0; i < NPW; i++) {
        int n = nbase + i;
        float a0 = 0.f, a1 = 0.f, g0 = 0.f, g1 = 0.f;
        if (n < NN) {
            int beg = d_rowptr[n], end = d_rowptr[n + 1];
            for (int j = beg; j < end; j++) {
                int2 cv = d_csr[j];
                float w = __int_as_float(cv.y);
                const float* xr = xin + cv.x * DD;
                a0 += w * xr[lane];
                a1 += w * xr[lane + 32];
            }
            float inv = 1.f / (float)max(end - beg, 1);
            a0 *= inv; a1 *= inv;
            g0 = d_xaggemb[n * DD + lane];
            g1 = d_xaggemb[n * DD + 32 + lane];
        }
        sv[lane * 4 + i]        = a0;
        sv[(lane + 32) * 4 + i] = a1;
        sv[(lane + 64) * 4 + i] = g0;
        sv[(lane + 96) * 4 + i] = g1;
    }
    __syncwarp();

    // Phase B: m = relu([x_agg, x_agg_emb] @ Wm + bm)
    float m0[NPW], m1[NPW];
    {
        float b0 = bm[lane], b1 = bm[lane + 32];
#pragma unroll
        for (int i = 0; i < NPW; i++) { m0[i] = b0; m1[i] = b1; }
    }
#pragma unroll 4
    for (int k = 0; k < 128; k++) {
        float w0 = sWm[k * DD + lane];
        float w1 = sWm[k * DD + lane + 32];
        float4 v = sv4[k];
        m0[0] += v.x * w0; m1[0] += v.x * w1;
        m0[1] += v.y * w0; m1[1] += v.y * w1;
        m0[2] += v.z * w0; m1[2] += v.z * w1;
        m0[3] += v.w * w0; m1[3] += v.w * w1;
    }
    __syncwarp();

    // Phase C: stage [x_emb_old, relu(m)]
#pragma unroll
    for (int i = 0; i < NPW; i++) {
        int n = nbase + i;
        float x0 = 0.f, x1 = 0.f;
        if (n < NN) {
            x0 = xin[n * DD + lane];
            x1 = xin[n * DD + 32 + lane];
        }
        sv[lane * 4 + i]        = x0;
        sv[(lane + 32) * 4 + i] = x1;
        sv[(lane + 64) * 4 + i] = fmaxf(m0[i], 0.f);
        sv[(lane + 96) * 4 + i] = fmaxf(m1[i], 0.f);
    }
    __syncwarp();

    // Phase D: x_emb_new = relu([x_emb, m] @ Wu + bu)
    float u0[NPW], u1[NPW];
    {
        float b0 = bu[lane], b1 = bu[lane + 32];
#pragma unroll
        for (int i = 0; i < NPW; i++) { u0[i] = b0; u1[i] = b1; }
    }
#pragma unroll 4
    for (int k = 0; k < 128; k++) {
        float w0 = sWu[k * DD + lane];
        float w1 = sWu[k * DD + lane + 32];
        float4 v = sv4[k];
        u0[0] += v.x * w0; u1[0] += v.x * w1;
        u0[1] += v.y * w0; u1[1] += v.y * w1;
        u0[2] += v.z * w0; u1[2] += v.z * w1;
        u0[3] += v.w * w0; u1[3] += v.w * w1;
    }
#pragma unroll
    for (int i = 0; i < NPW; i++) {
        int n = nbase + i;
        if (n < NN) {
            xout[n * DD + lane]      = fmaxf(u0[i], 0.f);
            xout[n * DD + 32 + lane] = fmaxf(u1[i], 0.f);
        }
    }
}

// ---------------- readout ----------------------------------------------------

__global__ void k_gsum() {
    __shared__ float sg[GG * DD];
    __shared__ int sc[GG];
    int t = threadIdx.x;
    for (int i = t; i < GG * DD; i += blockDim.x) sg[i] = 0.f;
    for (int i = t; i < GG; i += blockDim.x) sc[i] = 0;
    __syncthreads();
    int per = (NN + gridDim.x - 1) / gridDim.x;
    int nb = blockIdx.x * per;
    int ne = min(NN, nb + per);
    int col = t & 63, sub = t >> 6;
    for (int n = nb + sub; n < ne; n += 4) {
        int g = d_batch[n];
        atomicAdd(&sg[g * DD + col], d_e1[n * DD + col]);
        if (col == 0) atomicAdd(&sc[g], 1);
    }
    __syncthreads();
    for (int i = t; i < GG * DD; i += blockDim.x) atomicAdd(&d_gsum[i], sg[i]);
    for (int i = t; i < GG; i += blockDim.x) atomicAdd(&d_gcnt[i], sc[i]);
}

__global__ void k_gproj(const float* __restrict__ Wg, const float* __restrict__ bg) {
    int g = blockIdx.x, c = threadIdx.x;
    float inv = 1.f / (float)max(d_gcnt[g], 1);
    float s = bg[c];
    const float* row = d_gsum + g * DD;
#pragma unroll
    for (int k = 0; k < DD; k++) s += row[k] * inv * Wg[k * DD + c];
    d_rg[g * DD + c] = fmaxf(s, 0.f);
}

__global__ void k_final(const float* __restrict__ Wr, const float* __restrict__ br,
                        float* __restrict__ out) {
    int warp = (blockIdx.x * blockDim.x + threadIdx.x) >> 5;
    int lane = threadIdx.x & 31;
    if (warp >= NN) return;
    int n = warp;
    int g = d_batch[n];
    const float* rg = d_rg + g * DD;
    const float* xr = d_e1 + n * DD;
    float p = rg[lane] * Wr[lane] + rg[lane + 32] * Wr[lane + 32]
            + xr[lane] * Wr[64 + lane] + xr[lane + 32] * Wr[96 + lane];
#pragma unroll
    for (int off = 16; off; off >>= 1) p += __shfl_xor_sync(0xffffffffu, p, off);
    if (lane == 0) out[n] = p + br[0];
}

// ---------------- launch ------------------------------------------------------

extern "C" void kernel_launch(void* const* d_in, const int* in_sizes, int n_in,
                              void* d_out, int out_size) {
    int base = (n_in > 5 && in_sizes[5] == 1) ? 6 : 5;

    const float* x      = (const float*)d_in[0];
    const void*  ei     = d_in[1];
    const float* ea     = (const float*)d_in[2];
    const void*  batch  = d_in[3];
    const float* degree = (const float*)d_in[4];
    const float* W_en  = (const float*)d_in[base + 0];
    const float* b_en  = (const float*)d_in[base + 1];
    const float* W_ene = (const float*)d_in[base + 2];
    const float* b_ene = (const float*)d_in[base + 3];
    const float* W_agg = (const float*)d_in[base + 4];
    const float* b_agg = (const float*)d_in[base + 5];
    const float* Wm    = (const float*)d_in[base + 6];
    const float* bm    = (const float*)d_in[base + 7];
    const float* Wu    = (const float*)d_in[base + 8];
    const float* bu    = (const float*)d_in[base + 9];
    const float* W_g   = (const float*)d_in[base + 10];
    const float* b_g   = (const float*)d_in[base + 11];
    const float* W_r   = (const float*)d_in[base + 12];
    const float* b_r   = (const float*)d_in[base + 13];
    float* out = (float*)d_out;

    cudaFuncSetAttribute(k_layer, cudaFuncAttributeMaxDynamicSharedMemorySize, LAYER_SMEM);

    const int TB = 256;
    int gE  = (EE + TB - 1) / TB;
    int gND = (NN * DD + TB - 1) / TB;
    int gNW = (NN * 32 + TB - 1) / TB;

    k_zero<<<64, TB>>>();
    k_detect<<<gE, TB>>>((const long long*)ei);
    k_cvt_count<<<gE, TB>>>(ei, batch, degree);
    k_bsum<<<NSB, SCAN_B>>>();
    k_bscan<<<1, SCAN_B>>>();
    k_pscan<<<NSB, SCAN_B>>>();
    k_fill<<<gE, TB>>>(ei, ea);

    k_xemb<<<gND, TB>>>(x, W_en, b_en);
    k_ne<<<gNW, TB>>>(x, W_ene, b_ene);
    k_aggemb<<<gND, TB>>>(W_agg, b_agg);

    int nodes_per_blk = 8 * NPW;
    int gL = (NN + nodes_per_blk - 1) / nodes_per_blk;
    k_layer<<<gL, TB, LAYER_SMEM>>>(0, Wm + 0 * 8192, bm + 0 * 64, Wu + 0 * 8192, bu + 0 * 64);
    k_layer<<<gL, TB, LAYER_SMEM>>>(1, Wm + 1 * 8192, bm + 1 * 64, Wu + 1 * 8192, bu + 1 * 64);
    k_layer<<<gL, TB, LAYER_SMEM>>>(0, Wm + 2 * 8192, bm + 2 * 64, Wu + 2 * 8192, bu + 2 * 64);

    k_gsum<<<148, TB>>>();
    k_gproj<<<GG, DD>>>(W_g, b_g);
    k_final<<<gNW, TB>>>(W_r, b_r, out);

    (void)in_sizes; (void)n_in; (void)out_size; (void)degree;
}

// round 12
// speedup vs baseline: 1.8934x; 1.0534x over previous
#include <cuda_runtime.h>

#define NN 50000
#define EE 800000
#define DD 64
#define GG 64

#define SCAN_B 256
#define NSB ((NN + SCAN_B - 1) / SCAN_B)   // 196 blocks

// ---------------- scratch (device globals; accessed ONLY by symbol in device code)
__device__ int   d_is64 = 1;           // write-once 1->0 (deterministic across replays)
__device__ int   d_batch[NN];
__device__ int   d_deg[NN];
__device__ int   d_rowptr[NN + 1];
__device__ int   d_cursor[NN];
__device__ int2  d_csr[EE];            // (col, edge_attr float bits)
__device__ int   d_bsum[NSB];
__device__ int   d_degmaxbits[GG];     // per-graph max degree, float bits (degree >= 0)
__device__ float d_e0[NN * DD];        // x_emb ping
__device__ float d_e1[NN * DD];        // x_emb pong
__device__ float d_nein[NN * DD];      // [0:62] relu node_edge embed, [63] degree_norm
__device__ float d_xaggemb[NN * DD];   // x_agg_emb
__device__ float d_gsum[GG * DD];
__device__ int   d_gcnt[GG];
__device__ float d_rg[GG * DD];        // relu(g_agg @ W_g + b_g)

// ---------------- setup -----------------------------------------------------

// fused: per-launch zeroing + int64/int32 sniff.
// int32 data read as int64 lands out of [0,NN) somewhere among 800k elements,
// flipping d_is64 to 0 (it then stays 0; input is fixed across replays).
__global__ void k_detect_zero(const long long* __restrict__ ei) {
    int i = blockIdx.x * blockDim.x + threadIdx.x;
    int st = gridDim.x * blockDim.x;
    if (i < EE) {
        long long v = ei[i];
        if (v < 0 || v >= NN) d_is64 = 0;
    }
    for (int j = i; j < NN; j += st) d_deg[j] = 0;
    if (i < GG) { d_degmaxbits[i] = 0; d_gcnt[i] = 0; }
    if (i < GG * DD) d_gsum[i] = 0.f;
}

// fused: in-degree histogram + batch convert + per-graph degree max.
// degmax is staged through shared memory: global contended atomics drop from
// 50k (780/address serialized in L2) to <=196 blocks * #graphs-in-block.
__global__ void k_cvt_count(const void* __restrict__ ei, const void* __restrict__ bt,
                            const float* __restrict__ degree) {
    __shared__ int smax[GG];
    int i = blockIdx.x * blockDim.x + threadIdx.x;
    int t = threadIdx.x;
    int s = d_is64;
    bool node_blk = (blockIdx.x * blockDim.x) < NN;
    if (node_blk) {
        if (t < GG) smax[t] = 0;
        __syncthreads();
    }
    if (i < EE) {
        int r = s ? (int)((const long long*)ei)[EE + i] : ((const int*)ei)[EE + i];
        atomicAdd(&d_deg[r], 1);
    }
    if (i < NN) {
        int b = s ? (int)((const long long*)bt)[i] : ((const int*)bt)[i];
        d_batch[i] = b;
        atomicMax(&smax[b], __float_as_int(degree[i]));
    }
    if (node_blk) {
        __syncthreads();
        if (t < GG && smax[t] != 0) atomicMax(&d_degmaxbits[t], smax[t]);
    }
}

// ---- parallel exclusive scan of d_deg ----

__global__ void k_bsum() {
    __shared__ int s[SCAN_B];
    int t = threadIdx.x;
    int i = blockIdx.x * SCAN_B + t;
    s[t] = (i < NN) ? d_deg[i] : 0;
    __syncthreads();
    for (int off = SCAN_B / 2; off; off >>= 1) {
        if (t < off) s[t] += s[t + off];
        __syncthreads();
    }
    if (t == 0) d_bsum[blockIdx.x] = s[0];
}

// per-block scan with inline block-offset scan (bscan fused; NSB <= 256)
__global__ void k_pscan() {
    __shared__ int sb[SCAN_B];
    __shared__ int s[SCAN_B];
    int t = threadIdx.x;
    sb[t] = (t < NSB) ? d_bsum[t] : 0;
    int i = blockIdx.x * SCAN_B + t;
    int v = (i < NN) ? d_deg[i] : 0;
    s[t] = v;
    __syncthreads();
    for (int off = 1; off < SCAN_B; off <<= 1) {
        int a = (t >= off) ? sb[t - off] : 0;
        int b = (t >= off) ? s[t - off] : 0;
        __syncthreads();
        sb[t] += a;
        s[t] += b;
        __syncthreads();
    }
    int boff = (blockIdx.x == 0) ? 0 : sb[blockIdx.x - 1];
    int excl = s[t] - v + boff;
    if (i < NN) { d_rowptr[i] = excl; d_cursor[i] = excl; }
    if (i == 0) d_rowptr[NN] = EE;
}

// CSR fill straight from raw edge_index
__global__ void k_fill(const void* __restrict__ ei, const float* __restrict__ ea) {
    int e = blockIdx.x * blockDim.x + threadIdx.x;
    if (e >= EE) return;
    int s = d_is64;
    int c = s ? (int)((const long long*)ei)[e]      : ((const int*)ei)[e];
    int r = s ? (int)((const long long*)ei)[EE + e] : ((const int*)ei)[EE + e];
    int p = atomicAdd(&d_cursor[r], 1);
    d_csr[p] = make_int2(c, __float_as_int(ea[e]));
}

// ---------------- embeddings -------------------------------------------------

// x_emb = relu(x @ W_en + b_en) -> d_e0   (no deps; launched FIRST)
__global__ void k_xemb(const float* __restrict__ x, const float* __restrict__ W,
                       const float* __restrict__ b) {
    int i = blockIdx.x * blockDim.x + threadIdx.x;
    if (i >= NN * DD) return;
    int n = i >> 6, c = i & 63;
    const float* xr = x + n * 7;
    float s = b[c];
#pragma unroll
    for (int k = 0; k < 7; k++) s += xr[k] * W[k * DD + c];
    d_e0[i] = fmaxf(s, 0.f);
}

// node+edge embed: warp per node; mean of [x[col](7), edge_attr(1)] -> GEMV 8x63 relu
__global__ void k_ne(const float* __restrict__ x, const float* __restrict__ W,
                     const float* __restrict__ b) {
    int warp = (blockIdx.x * blockDim.x + threadIdx.x) >> 5;
    int lane = threadIdx.x & 31;
    if (warp >= NN) return;
    int n = warp;
    int beg = d_rowptr[n], end = d_rowptr[n + 1];
    float acc[8] = {0, 0, 0, 0, 0, 0, 0, 0};
    for (int j = beg + lane; j < end; j += 32) {
        int2 cv = d_csr[j];
        const float* xr = x + cv.x * 7;
#pragma unroll
        for (int k = 0; k < 7; k++) acc[k] += xr[k];
        acc[7] += __int_as_float(cv.y);
    }
#pragma unroll
    for (int k = 0; k < 8; k++)
#pragma unroll
        for (int off = 16; off; off >>= 1) acc[k] += __shfl_xor_sync(0xffffffffu, acc[k], off);
    float inv = 1.f / (float)max(end - beg, 1);
#pragma unroll
    for (int k = 0; k < 8; k++) acc[k] *= inv;
    float o0 = b[lane];
    float o1 = (lane < 31) ? b[lane + 32] : 0.f;
#pragma unroll
    for (int k = 0; k < 8; k++) {
        o0 += acc[k] * W[k * 63 + lane];
        if (lane < 31) o1 += acc[k] * W[k * 63 + lane + 32];
    }
    d_nein[n * DD + lane] = fmaxf(o0, 0.f);
    if (lane < 31) d_nein[n * DD + 32 + lane] = fmaxf(o1, 0.f);
    if (lane == 31) d_nein[n * DD + 63] = __int_as_float(d_degmaxbits[d_batch[n]]);
}

// x_agg_emb = relu([node_edge, degree_norm] @ W_agg + b_agg)
__global__ void k_aggemb(const float* __restrict__ W, const float* __restrict__ b) {
    int i = blockIdx.x * blockDim.x + threadIdx.x;
    if (i >= NN * DD) return;
    int n = i >> 6, c = i & 63;
    const float* in = d_nein + n * DD;
    float s = b[c];
#pragma unroll
    for (int k = 0; k < DD; k++) s += in[k] * W[k * DD + c];
    d_xaggemb[i] = fmaxf(s, 0.f);
}

// ---------------- fused message-passing layer (R11 proven config) ------------
// 1563 blocks, 8 warps, 4 nodes/warp; staging [k][node] -> LDS.128 broadcast
// dyn smem: Wm 32KB + Wu 32KB + staging 8 warps * 2KB = 80KB

#define NPW 4
#define LAYER_SMEM ((8192 + 8192 + 8 * NPW * 128) * (int)sizeof(float))

__global__ void __launch_bounds__(256) k_layer(
    int flip,   // 0: e0 -> e1 ; 1: e1 -> e0
    const float* __restrict__ Wm, const float* __restrict__ bm,
    const float* __restrict__ Wu, const float* __restrict__ bu) {
    const float* xin  = flip ? d_e1 : d_e0;
    float*       xout = flip ? d_e0 : d_e1;
    extern __shared__ float sm[];
    float* sWm = sm;
    float* sWu = sm + 8192;
    float* sIn = sm + 16384;
    int t = threadIdx.x;
    for (int i = t; i < 8192; i += 256) { sWm[i] = Wm[i]; sWu[i] = Wu[i]; }
    __syncthreads();

    int warp = t >> 5, lane = t & 31;
    float* sv = sIn + warp * (NPW * 128);           // [k in 0..127][i in 0..3]
    const float4* sv4 = (const float4*)sv;
    int nbase = blockIdx.x * (8 * NPW) + warp * NPW;

    // Phase A: x_agg = mean_{e->n} ea[e]*xin[col[e]]; stage [x_agg, x_agg_emb]
#pragma unroll
    for (int i = 0; i < NPW; i++) {
        int n = nbase + i;
        float a0 = 0.f, a1 = 0.f, g0 = 0.f, g1 = 0.f;
        if (n < NN) {
            int beg = d_rowptr[n], end = d_rowptr[n + 1];
            for (int j = beg; j < end; j++) {
                int2 cv = d_csr[j];
                float w = __int_as_float(cv.y);
                const float* xr = xin + cv.x * DD;
                a0 += w * xr[lane];
                a1 += w * xr[lane + 32];
            }
            float inv = 1.f / (float)max(end - beg, 1);
            a0 *= inv; a1 *= inv;
            g0 = d_xaggemb[n * DD + lane];
            g1 = d_xaggemb[n * DD + 32 + lane];
        }
        sv[lane * 4 + i]        = a0;
        sv[(lane + 32) * 4 + i] = a1;
        sv[(lane + 64) * 4 + i] = g0;
        sv[(lane + 96) * 4 + i] = g1;
    }
    __syncwarp();

    // Phase B: m = relu([x_agg, x_agg_emb] @ Wm + bm)
    float m0[NPW], m1[NPW];
    {
        float b0 = bm[lane], b1 = bm[lane + 32];
#pragma unroll
        for (int i = 0; i < NPW; i++) { m0[i] = b0; m1[i] = b1; }
    }
#pragma unroll 4
    for (int k = 0; k < 128; k++) {
        float w0 = sWm[k * DD + lane];
        float w1 = sWm[k * DD + lane + 32];
        float4 v = sv4[k];
        m0[0] += v.x * w0; m1[0] += v.x * w1;
        m0[1] += v.y * w0; m1[1] += v.y * w1;
        m0[2] += v.z * w0; m1[2] += v.z * w1;
        m0[3] += v.w * w0; m1[3] += v.w * w1;
    }
    __syncwarp();

    // Phase C: stage [x_emb_old, relu(m)]
#pragma unroll
    for (int i = 0; i < NPW; i++) {
        int n = nbase + i;
        float x0 = 0.f, x1 = 0.f;
        if (n < NN) {
            x0 = xin[n * DD + lane];
            x1 = xin[n * DD + 32 + lane];
        }
        sv[lane * 4 + i]        = x0;
        sv[(lane + 32) * 4 + i] = x1;
        sv[(lane + 64) * 4 + i] = fmaxf(m0[i], 0.f);
        sv[(lane + 96) * 4 + i] = fmaxf(m1[i], 0.f);
    }
    __syncwarp();

    // Phase D: x_emb_new = relu([x_emb, m] @ Wu + bu)
    float u0[NPW], u1[NPW];
    {
        float b0 = bu[lane], b1 = bu[lane + 32];
#pragma unroll
        for (int i = 0; i < NPW; i++) { u0[i] = b0; u1[i] = b1; }
    }
#pragma unroll 4
    for (int k = 0; k < 128; k++) {
        float w0 = sWu[k * DD + lane];
        float w1 = sWu[k * DD + lane + 32];
        float4 v = sv4[k];
        u0[0] += v.x * w0; u1[0] += v.x * w1;
        u0[1] += v.y * w0; u1[1] += v.y * w1;
        u0[2] += v.z * w0; u1[2] += v.z * w1;
        u0[3] += v.w * w0; u1[3] += v.w * w1;
    }
#pragma unroll
    for (int i = 0; i < NPW; i++) {
        int n = nbase + i;
        if (n < NN) {
            xout[n * DD + lane]      = fmaxf(u0[i], 0.f);
            xout[n * DD + 32 + lane] = fmaxf(u1[i], 0.f);
        }
    }
}

// ---------------- readout ----------------------------------------------------

__global__ void k_gsum() {
    __shared__ float sg[GG * DD];
    __shared__ int sc[GG];
    int t = threadIdx.x;
    for (int i = t; i < GG * DD; i += blockDim.x) sg[i] = 0.f;
    for (int i = t; i < GG; i += blockDim.x) sc[i] = 0;
    __syncthreads();
    int per = (NN + gridDim.x - 1) / gridDim.x;
    int nb = blockIdx.x * per;
    int ne = min(NN, nb + per);
    int col = t & 63, sub = t >> 6;
    for (int n = nb + sub; n < ne; n += 4) {
        int g = d_batch[n];
        atomicAdd(&sg[g * DD + col], d_e1[n * DD + col]);
        if (col == 0) atomicAdd(&sc[g], 1);
    }
    __syncthreads();
    for (int i = t; i < GG * DD; i += blockDim.x) atomicAdd(&d_gsum[i], sg[i]);
    for (int i = t; i < GG; i += blockDim.x) atomicAdd(&d_gcnt[i], sc[i]);
}

__global__ void k_gproj(const float* __restrict__ Wg, const float* __restrict__ bg) {
    int g = blockIdx.x, c = threadIdx.x;
    float inv = 1.f / (float)max(d_gcnt[g], 1);
    float s = bg[c];
    const float* row = d_gsum + g * DD;
#pragma unroll
    for (int k = 0; k < DD; k++) s += row[k] * inv * Wg[k * DD + c];
    d_rg[g * DD + c] = fmaxf(s, 0.f);
}

__global__ void k_final(const float* __restrict__ Wr, const float* __restrict__ br,
                        float* __restrict__ out) {
    int warp = (blockIdx.x * blockDim.x + threadIdx.x) >> 5;
    int lane = threadIdx.x & 31;
    if (warp >= NN) return;
    int n = warp;
    int g = d_batch[n];
    const float* rg = d_rg + g * DD;
    const float* xr = d_e1 + n * DD;
    float p = rg[lane] * Wr[lane] + rg[lane + 32] * Wr[lane + 32]
            + xr[lane] * Wr[64 + lane] + xr[lane + 32] * Wr[96 + lane];
#pragma unroll
    for (int off = 16; off; off >>= 1) p += __shfl_xor_sync(0xffffffffu, p, off);
    if (lane == 0) out[n] = p + br[0];
}

// ---------------- launch ------------------------------------------------------

extern "C" void kernel_launch(void* const* d_in, const int* in_sizes, int n_in,
                              void* d_out, int out_size) {
    int base = (n_in > 5 && in_sizes[5] == 1) ? 6 : 5;

    const float* x      = (const float*)d_in[0];
    const void*  ei     = d_in[1];
    const float* ea     = (const float*)d_in[2];
    const void*  batch  = d_in[3];
    const float* degree = (const float*)d_in[4];
    const float* W_en  = (const float*)d_in[base + 0];
    const float* b_en  = (const float*)d_in[base + 1];
    const float* W_ene = (const float*)d_in[base + 2];
    const float* b_ene = (const float*)d_in[base + 3];
    const float* W_agg = (const float*)d_in[base + 4];
    const float* b_agg = (const float*)d_in[base + 5];
    const float* Wm    = (const float*)d_in[base + 6];
    const float* bm    = (const float*)d_in[base + 7];
    const float* Wu    = (const float*)d_in[base + 8];
    const float* bu    = (const float*)d_in[base + 9];
    const float* W_g   = (const float*)d_in[base + 10];
    const float* b_g   = (const float*)d_in[base + 11];
    const float* W_r   = (const float*)d_in[base + 12];
    const float* b_r   = (const float*)d_in[base + 13];
    float* out = (float*)d_out;

    cudaFuncSetAttribute(k_layer, cudaFuncAttributeMaxDynamicSharedMemorySize, LAYER_SMEM);

    const int TB = 256;
    int gE  = (EE + TB - 1) / TB;
    int gND = (NN * DD + TB - 1) / TB;
    int gNW = (NN * 32 + TB - 1) / TB;

    k_xemb<<<gND, TB>>>(x, W_en, b_en);                 // 1 (independent; fronted)
    k_detect_zero<<<gE, TB>>>((const long long*)ei);    // 2
    k_cvt_count<<<gE, TB>>>(ei, batch, degree);         // 3
    k_bsum<<<NSB, SCAN_B>>>();                          // 4
    k_pscan<<<NSB, SCAN_B>>>();                         // 5
    k_fill<<<gE, TB>>>(ei, ea);                         // 6  <- ncu -s 5 -c 1 target

    k_ne<<<gNW, TB>>>(x, W_ene, b_ene);
    k_aggemb<<<gND, TB>>>(W_agg, b_agg);

    int nodes_per_blk = 8 * NPW;
    int gL = (NN + nodes_per_blk - 1) / nodes_per_blk;
    k_layer<<<gL, TB, LAYER_SMEM>>>(0, Wm + 0 * 8192, bm + 0 * 64, Wu + 0 * 8192, bu + 0 * 64);
    k_layer<<<gL, TB, LAYER_SMEM>>>(1, Wm + 1 * 8192, bm + 1 * 64, Wu + 1 * 8192, bu + 1 * 64);
    k_layer<<<gL, TB, LAYER_SMEM>>>(0, Wm + 2 * 8192, bm + 2 * 64, Wu + 2 * 8192, bu + 2 * 64);

    k_gsum<<<148, TB>>>();
    k_gproj<<<GG, DD>>>(W_g, b_g);
    k_final<<<gNW, TB>>>(W_r, b_r, out);

    (void)in_sizes; (void)n_in; (void)out_size; (void)degree;
}

// round 13
// speedup vs baseline: 2.2371x; 1.1816x over previous
#include <cuda_runtime.h>

#define NN 50000
#define EE 800000
#define DD 64
#define GG 64

#define SCAN_B 256
#define NSB ((NN + SCAN_B - 1) / SCAN_B)   // 196 blocks

// ---------------- scratch (device globals; accessed ONLY by symbol in device code)
__device__ int   d_is64 = 1;           // write-once 1->0 (deterministic across replays)
__device__ int   d_batch[NN];
__device__ int   d_deg[NN];
__device__ int   d_rowptr[NN + 1];
__device__ int   d_cursor[NN];
__device__ int2  d_csr[EE];            // (col, edge_attr float bits)
__device__ int   d_bsum[NSB];
__device__ int   d_degmaxbits[GG];     // per-graph max degree, float bits (degree >= 0)
__device__ float d_e0[NN * DD];        // x_emb ping
__device__ float d_e1[NN * DD];        // x_emb pong
__device__ float d_nein[NN * DD];      // [0:62] relu node_edge embed, [63] degree_norm
__device__ float d_xaggemb[NN * DD];   // x_agg_emb
__device__ float d_gsum[GG * DD];
__device__ int   d_gcnt[GG];
__device__ float d_rg[GG * DD];        // relu(g_agg @ W_g + b_g)

// ---------------- setup -----------------------------------------------------

// fused: per-launch zeroing + int64/int32 sniff.
__global__ void k_detect_zero(const long long* __restrict__ ei) {
    int i = blockIdx.x * blockDim.x + threadIdx.x;
    int st = gridDim.x * blockDim.x;
    if (i < EE) {
        long long v = ei[i];
        if (v < 0 || v >= NN) d_is64 = 0;
    }
    for (int j = i; j < NN; j += st) d_deg[j] = 0;
    if (i < GG) { d_degmaxbits[i] = 0; d_gcnt[i] = 0; }
    if (i < GG * DD) d_gsum[i] = 0.f;
}

// fused: in-degree histogram + batch convert + smem-staged per-graph degree max
__global__ void k_cvt_count(const void* __restrict__ ei, const void* __restrict__ bt,
                            const float* __restrict__ degree) {
    __shared__ int smax[GG];
    int i = blockIdx.x * blockDim.x + threadIdx.x;
    int t = threadIdx.x;
    int s = d_is64;
    bool node_blk = (blockIdx.x * blockDim.x) < NN;
    if (node_blk) {
        if (t < GG) smax[t] = 0;
        __syncthreads();
    }
    if (i < EE) {
        int r = s ? (int)((const long long*)ei)[EE + i] : ((const int*)ei)[EE + i];
        atomicAdd(&d_deg[r], 1);
    }
    if (i < NN) {
        int b = s ? (int)((const long long*)bt)[i] : ((const int*)bt)[i];
        d_batch[i] = b;
        atomicMax(&smax[b], __float_as_int(degree[i]));
    }
    if (node_blk) {
        __syncthreads();
        if (t < GG && smax[t] != 0) atomicMax(&d_degmaxbits[t], smax[t]);
    }
}

// ---- parallel exclusive scan of d_deg ----

__global__ void k_bsum() {
    __shared__ int s[SCAN_B];
    int t = threadIdx.x;
    int i = blockIdx.x * SCAN_B + t;
    s[t] = (i < NN) ? d_deg[i] : 0;
    __syncthreads();
    for (int off = SCAN_B / 2; off; off >>= 1) {
        if (t < off) s[t] += s[t + off];
        __syncthreads();
    }
    if (t == 0) d_bsum[blockIdx.x] = s[0];
}

// per-block scan with inline block-offset scan (NSB <= 256)
__global__ void k_pscan() {
    __shared__ int sb[SCAN_B];
    __shared__ int s[SCAN_B];
    int t = threadIdx.x;
    sb[t] = (t < NSB) ? d_bsum[t] : 0;
    int i = blockIdx.x * SCAN_B + t;
    int v = (i < NN) ? d_deg[i] : 0;
    s[t] = v;
    __syncthreads();
    for (int off = 1; off < SCAN_B; off <<= 1) {
        int a = (t >= off) ? sb[t - off] : 0;
        int b = (t >= off) ? s[t - off] : 0;
        __syncthreads();
        sb[t] += a;
        s[t] += b;
        __syncthreads();
    }
    int boff = (blockIdx.x == 0) ? 0 : sb[blockIdx.x - 1];
    int excl = s[t] - v + boff;
    if (i < NN) { d_rowptr[i] = excl; d_cursor[i] = excl; }
    if (i == 0) d_rowptr[NN] = EE;
}

// CSR fill straight from raw edge_index
__global__ void k_fill(const void* __restrict__ ei, const float* __restrict__ ea) {
    int e = blockIdx.x * blockDim.x + threadIdx.x;
    if (e >= EE) return;
    int s = d_is64;
    int c = s ? (int)((const long long*)ei)[e]      : ((const int*)ei)[e];
    int r = s ? (int)((const long long*)ei)[EE + e] : ((const int*)ei)[EE + e];
    int p = atomicAdd(&d_cursor[r], 1);
    d_csr[p] = make_int2(c, __float_as_int(ea[e]));
}

// ---------------- embeddings -------------------------------------------------

// x_emb = relu(x @ W_en + b_en) -> d_e0   (independent; fronted)
__global__ void k_xemb(const float* __restrict__ x, const float* __restrict__ W,
                       const float* __restrict__ b) {
    int i = blockIdx.x * blockDim.x + threadIdx.x;
    if (i >= NN * DD) return;
    int n = i >> 6, c = i & 63;
    const float* xr = x + n * 7;
    float s = b[c];
#pragma unroll
    for (int k = 0; k < 7; k++) s += xr[k] * W[k * DD + c];
    d_e0[i] = fmaxf(s, 0.f);
}

// node+edge embed: warp per node; mean of [x[col](7), edge_attr(1)] -> GEMV 8x63 relu
__global__ void k_ne(const float* __restrict__ x, const float* __restrict__ W,
                     const float* __restrict__ b) {
    int warp = (blockIdx.x * blockDim.x + threadIdx.x) >> 5;
    int lane = threadIdx.x & 31;
    if (warp >= NN) return;
    int n = warp;
    int beg = d_rowptr[n], end = d_rowptr[n + 1];
    float acc[8] = {0, 0, 0, 0, 0, 0, 0, 0};
    for (int j = beg + lane; j < end; j += 32) {
        int2 cv = d_csr[j];
        const float* xr = x + cv.x * 7;
#pragma unroll
        for (int k = 0; k < 7; k++) acc[k] += xr[k];
        acc[7] += __int_as_float(cv.y);
    }
#pragma unroll
    for (int k = 0; k < 8; k++)
#pragma unroll
        for (int off = 16; off; off >>= 1) acc[k] += __shfl_xor_sync(0xffffffffu, acc[k], off);
    float inv = 1.f / (float)max(end - beg, 1);
#pragma unroll
    for (int k = 0; k < 8; k++) acc[k] *= inv;
    float o0 = b[lane];
    float o1 = (lane < 31) ? b[lane + 32] : 0.f;
#pragma unroll
    for (int k = 0; k < 8; k++) {
        o0 += acc[k] * W[k * 63 + lane];
        if (lane < 31) o1 += acc[k] * W[k * 63 + lane + 32];
    }
    d_nein[n * DD + lane] = fmaxf(o0, 0.f);
    if (lane < 31) d_nein[n * DD + 32 + lane] = fmaxf(o1, 0.f);
    if (lane == 31) d_nein[n * DD + 63] = __int_as_float(d_degmaxbits[d_batch[n]]);
}

// x_agg_emb = relu([node_edge, degree_norm] @ W_agg + b_agg)
__global__ void k_aggemb(const float* __restrict__ W, const float* __restrict__ b) {
    int i = blockIdx.x * blockDim.x + threadIdx.x;
    if (i >= NN * DD) return;
    int n = i >> 6, c = i & 63;
    const float* in = d_nein + n * DD;
    float s = b[c];
#pragma unroll
    for (int k = 0; k < DD; k++) s += in[k] * W[k * DD + c];
    d_xaggemb[i] = fmaxf(s, 0.f);
}

// ---------------- fused message-passing layer --------------------------------
// 512 thr = 16 warps (8 warps/SMSP at 2 blocks/SM -> 2x latency hiding vs R12),
// warp owns 4 nodes; staging [k][node] -> LDS.128 broadcast in MLP loops.
// Phase A edge loop unrolled x2 with dual accumulators (2 load chains in flight).
// dyn smem: Wm 32KB + Wu 32KB + staging 16 warps * 2KB = 96KB

#define NPW 4
#define TBL 512
#define WPB 16
#define LAYER_SMEM ((8192 + 8192 + WPB * NPW * 128) * (int)sizeof(float))

__global__ void __launch_bounds__(TBL) k_layer(
    int flip,   // 0: e0 -> e1 ; 1: e1 -> e0
    const float* __restrict__ Wm, const float* __restrict__ bm,
    const float* __restrict__ Wu, const float* __restrict__ bu) {
    const float* xin  = flip ? d_e1 : d_e0;
    float*       xout = flip ? d_e0 : d_e1;
    extern __shared__ float sm[];
    float* sWm = sm;
    float* sWu = sm + 8192;
    float* sIn = sm + 16384;
    int t = threadIdx.x;
    for (int i = t; i < 8192; i += TBL) { sWm[i] = Wm[i]; sWu[i] = Wu[i]; }
    __syncthreads();

    int warp = t >> 5, lane = t & 31;
    float* sv = sIn + warp * (NPW * 128);           // [k in 0..127][i in 0..3]
    const float4* sv4 = (const float4*)sv;
    int nbase = blockIdx.x * (WPB * NPW) + warp * NPW;

    // Phase A: x_agg = mean_{e->n} ea[e]*xin[col[e]]; stage [x_agg, x_agg_emb]
#pragma unroll
    for (int i = 0; i < NPW; i++) {
        int n = nbase + i;
        float a0 = 0.f, a1 = 0.f, g0 = 0.f, g1 = 0.f;
        if (n < NN) {
            int beg = d_rowptr[n], end = d_rowptr[n + 1];
            float c0 = 0.f, c1 = 0.f;       // second chain
            int j = beg;
            for (; j + 1 < end; j += 2) {
                int2 cva = d_csr[j];
                int2 cvb = d_csr[j + 1];
                float wa = __int_as_float(cva.y);
                float wb = __int_as_float(cvb.y);
                const float* xra = xin + cva.x * DD;
                const float* xrb = xin + cvb.x * DD;
                a0 += wa * xra[lane];
                a1 += wa * xra[lane + 32];
                c0 += wb * xrb[lane];
                c1 += wb * xrb[lane + 32];
            }
            if (j < end) {
                int2 cv = d_csr[j];
                float w = __int_as_float(cv.y);
                const float* xr = xin + cv.x * DD;
                a0 += w * xr[lane];
                a1 += w * xr[lane + 32];
            }
            a0 += c0; a1 += c1;
            float inv = 1.f / (float)max(end - beg, 1);
            a0 *= inv; a1 *= inv;
            g0 = d_xaggemb[n * DD + lane];
            g1 = d_xaggemb[n * DD + 32 + lane];
        }
        sv[lane * 4 + i]        = a0;
        sv[(lane + 32) * 4 + i] = a1;
        sv[(lane + 64) * 4 + i] = g0;
        sv[(lane + 96) * 4 + i] = g1;
    }
    __syncwarp();

    // Phase B: m = relu([x_agg, x_agg_emb] @ Wm + bm)
    float m0[NPW], m1[NPW];
    {
        float b0 = bm[lane], b1 = bm[lane + 32];
#pragma unroll
        for (int i = 0; i < NPW; i++) { m0[i] = b0; m1[i] = b1; }
    }
#pragma unroll 4
    for (int k = 0; k < 128; k++) {
        float w0 = sWm[k * DD + lane];
        float w1 = sWm[k * DD + lane + 32];
        float4 v = sv4[k];
        m0[0] += v.x * w0; m1[0] += v.x * w1;
        m0[1] += v.y * w0; m1[1] += v.y * w1;
        m0[2] += v.z * w0; m1[2] += v.z * w1;
        m0[3] += v.w * w0; m1[3] += v.w * w1;
    }
    __syncwarp();

    // Phase C: stage [x_emb_old, relu(m)]
#pragma unroll
    for (int i = 0; i < NPW; i++) {
        int n = nbase + i;
        float x0 = 0.f, x1 = 0.f;
        if (n < NN) {
            x0 = xin[n * DD + lane];
            x1 = xin[n * DD + 32 + lane];
        }
        sv[lane * 4 + i]        = x0;
        sv[(lane + 32) * 4 + i] = x1;
        sv[(lane + 64) * 4 + i] = fmaxf(m0[i], 0.f);
        sv[(lane + 96) * 4 + i] = fmaxf(m1[i], 0.f);
    }
    __syncwarp();

    // Phase D: x_emb_new = relu([x_emb, m] @ Wu + bu)
    float u0[NPW], u1[NPW];
    {
        float b0 = bu[lane], b1 = bu[lane + 32];
#pragma unroll
        for (int i = 0; i < NPW; i++) { u0[i] = b0; u1[i] = b1; }
    }
#pragma unroll 4
    for (int k = 0; k < 128; k++) {
        float w0 = sWu[k * DD + lane];
        float w1 = sWu[k * DD + lane + 32];
        float4 v = sv4[k];
        u0[0] += v.x * w0; u1[0] += v.x * w1;
        u0[1] += v.y * w0; u1[1] += v.y * w1;
        u0[2] += v.z * w0; u1[2] += v.z * w1;
        u0[3] += v.w * w0; u1[3] += v.w * w1;
    }
#pragma unroll
    for (int i = 0; i < NPW; i++) {
        int n = nbase + i;
        if (n < NN) {
            xout[n * DD + lane]      = fmaxf(u0[i], 0.f);
            xout[n * DD + 32 + lane] = fmaxf(u1[i], 0.f);
        }
    }
}

// ---------------- readout ----------------------------------------------------

__global__ void k_gsum() {
    __shared__ float sg[GG * DD];
    __shared__ int sc[GG];
    int t = threadIdx.x;
    for (int i = t; i < GG * DD; i += blockDim.x) sg[i] = 0.f;
    for (int i = t; i < GG; i += blockDim.x) sc[i] = 0;
    __syncthreads();
    int per = (NN + gridDim.x - 1) / gridDim.x;
    int nb = blockIdx.x * per;
    int ne = min(NN, nb + per);
    int col = t & 63, sub = t >> 6;
    for (int n = nb + sub; n < ne; n += 4) {
        int g = d_batch[n];
        atomicAdd(&sg[g * DD + col], d_e1[n * DD + col]);
        if (col == 0) atomicAdd(&sc[g], 1);
    }
    __syncthreads();
    for (int i = t; i < GG * DD; i += blockDim.x) atomicAdd(&d_gsum[i], sg[i]);
    for (int i = t; i < GG; i += blockDim.x) atomicAdd(&d_gcnt[i], sc[i]);
}

__global__ void k_gproj(const float* __restrict__ Wg, const float* __restrict__ bg) {
    int g = blockIdx.x, c = threadIdx.x;
    float inv = 1.f / (float)max(d_gcnt[g], 1);
    float s = bg[c];
    const float* row = d_gsum + g * DD;
#pragma unroll
    for (int k = 0; k < DD; k++) s += row[k] * inv * Wg[k * DD + c];
    d_rg[g * DD + c] = fmaxf(s, 0.f);
}

__global__ void k_final(const float* __restrict__ Wr, const float* __restrict__ br,
                        float* __restrict__ out) {
    int warp = (blockIdx.x * blockDim.x + threadIdx.x) >> 5;
    int lane = threadIdx.x & 31;
    if (warp >= NN) return;
    int n = warp;
    int g = d_batch[n];
    const float* rg = d_rg + g * DD;
    const float* xr = d_e1 + n * DD;
    float p = rg[lane] * Wr[lane] + rg[lane + 32] * Wr[lane + 32]
            + xr[lane] * Wr[64 + lane] + xr[lane + 32] * Wr[96 + lane];
#pragma unroll
    for (int off = 16; off; off >>= 1) p += __shfl_xor_sync(0xffffffffu, p, off);
    if (lane == 0) out[n] = p + br[0];
}

// ---------------- launch ------------------------------------------------------

extern "C" void kernel_launch(void* const* d_in, const int* in_sizes, int n_in,
                              void* d_out, int out_size) {
    int base = (n_in > 5 && in_sizes[5] == 1) ? 6 : 5;

    const float* x      = (const float*)d_in[0];
    const void*  ei     = d_in[1];
    const float* ea     = (const float*)d_in[2];
    const void*  batch  = d_in[3];
    const float* degree = (const float*)d_in[4];
    const float* W_en  = (const float*)d_in[base + 0];
    const float* b_en  = (const float*)d_in[base + 1];
    const float* W_ene = (const float*)d_in[base + 2];
    const float* b_ene = (const float*)d_in[base + 3];
    const float* W_agg = (const float*)d_in[base + 4];
    const float* b_agg = (const float*)d_in[base + 5];
    const float* Wm    = (const float*)d_in[base + 6];
    const float* bm    = (const float*)d_in[base + 7];
    const float* Wu    = (const float*)d_in[base + 8];
    const float* bu    = (const float*)d_in[base + 9];
    const float* W_g   = (const float*)d_in[base + 10];
    const float* b_g   = (const float*)d_in[base + 11];
    const float* W_r   = (const float*)d_in[base + 12];
    const float* b_r   = (const float*)d_in[base + 13];
    float* out = (float*)d_out;

    cudaFuncSetAttribute(k_layer, cudaFuncAttributeMaxDynamicSharedMemorySize, LAYER_SMEM);

    const int TB = 256;
    int gE  = (EE + TB - 1) / TB;
    int gND = (NN * DD + TB - 1) / TB;
    int gNW = (NN * 32 + TB - 1) / TB;

    k_xemb<<<gND, TB>>>(x, W_en, b_en);
    k_detect_zero<<<gE, TB>>>((const long long*)ei);
    k_cvt_count<<<gE, TB>>>(ei, batch, degree);
    k_bsum<<<NSB, SCAN_B>>>();
    k_pscan<<<NSB, SCAN_B>>>();
    k_fill<<<gE, TB>>>(ei, ea);

    k_ne<<<gNW, TB>>>(x, W_ene, b_ene);
    k_aggemb<<<gND, TB>>>(W_agg, b_agg);

    int nodes_per_blk = WPB * NPW;   // 64
    int gL = (NN + nodes_per_blk - 1) / nodes_per_blk;   // 782
    k_layer<<<gL, TBL, LAYER_SMEM>>>(0, Wm + 0 * 8192, bm + 0 * 64, Wu + 0 * 8192, bu + 0 * 64);
    k_layer<<<gL, TBL, LAYER_SMEM>>>(1, Wm + 1 * 8192, bm + 1 * 64, Wu + 1 * 8192, bu + 1 * 64);
    k_layer<<<gL, TBL, LAYER_SMEM>>>(0, Wm + 2 * 8192, bm + 2 * 64, Wu + 2 * 8192, bu + 2 * 64);

    k_gsum<<<148, TB>>>();
    k_gproj<<<GG, DD>>>(W_g, b_g);
    k_final<<<gNW, TB>>>(W_r, b_r, out);

    (void)in_sizes; (void)n_in; (void)out_size; (void)degree;
}